// round 15
// baseline (speedup 1.0000x reference)
#include <cuda_runtime.h>
#include <cuda_bf16.h>
#include <cstdint>
#include <math.h>

#define NN 50000
#define NE 800000
#define TT 12
#define NPB 128
#define THREADS 128
#define SCAN_BLOCKS 196   // ceil(50000/256)

// ---------------- device scratch (no allocations) ----------------
__device__ int   g_cnt[NN];
__device__ int   g_off[NN];
__device__ int   g_fill[NN];
__device__ int   g_srcs[NE];
__device__ float g_dinv[NN];
__device__ float g_agg[NN * 24];    // raw: sum_e dinv[src]*x[src][c]
__device__ int   g_bsum[256];
__device__ int   g_bpre[256];
__device__ int   g_is64;

// ---------------- preprocessing: CSR build + gather ----------------
__global__ void k_initprobe(const int* __restrict__ ei32) {
    int i = blockIdx.x * blockDim.x + threadIdx.x;
    int stride = gridDim.x * blockDim.x;
    for (int j = i; j < NN; j += stride) g_cnt[j] = 0;
    if (blockIdx.x == 0) {
        int nz = 0;
        for (int j = threadIdx.x; j < 1024; j += blockDim.x)
            if (ei32[2 * j + 1] != 0) nz = 1;
        int any = __syncthreads_or(nz);
        if (threadIdx.x == 0) g_is64 = any ? 0 : 1;
    }
}

__device__ __forceinline__ void load_edge(const int* ei32, int e, int& s, int& d) {
    if (g_is64) { s = ei32[2 * e]; d = ei32[2 * (NE + e)]; }
    else        { s = ei32[e];     d = ei32[NE + e]; }
}

__global__ void k_count(const int* __restrict__ ei32) {
    int e = blockIdx.x * blockDim.x + threadIdx.x;
    if (e >= NE) return;
    int s, d;
    load_edge(ei32, e, s, d);
    atomicAdd(&g_cnt[d], 1);
}

__global__ void k_scan1() {
    __shared__ int sc[256];
    int tid = threadIdx.x;
    int i = blockIdx.x * 256 + tid;
    int v = (i < NN) ? g_cnt[i] : 0;
    sc[tid] = v;
    __syncthreads();
#pragma unroll
    for (int ofs = 1; ofs < 256; ofs <<= 1) {
        int t = (tid >= ofs) ? sc[tid - ofs] : 0;
        __syncthreads();
        sc[tid] += t;
        __syncthreads();
    }
    if (i < NN) g_off[i] = sc[tid] - v;
    if (tid == 255) g_bsum[blockIdx.x] = sc[255];
}

__global__ void k_scan2() {
    __shared__ int sc[256];
    int tid = threadIdx.x;
    int v = (tid < SCAN_BLOCKS) ? g_bsum[tid] : 0;
    sc[tid] = v;
    __syncthreads();
#pragma unroll
    for (int ofs = 1; ofs < 256; ofs <<= 1) {
        int t = (tid >= ofs) ? sc[tid - ofs] : 0;
        __syncthreads();
        sc[tid] += t;
        __syncthreads();
    }
    g_bpre[tid] = sc[tid] - v;
}

__global__ void k_scan3() {
    int i = blockIdx.x * 256 + threadIdx.x;
    if (i >= NN) return;
    int off = g_off[i] + g_bpre[blockIdx.x];
    g_off[i]  = off;
    g_fill[i] = off;
    g_dinv[i] = rsqrtf((float)g_cnt[i] + 1.0f);
}

__global__ void k_fill(const int* __restrict__ ei32) {
    int e = blockIdx.x * blockDim.x + threadIdx.x;
    if (e >= NE) return;
    int s, d;
    load_edge(ei32, e, s, d);
    int pos = atomicAdd(&g_fill[d], 1);
    g_srcs[pos] = s;
}

__global__ void k_gather(const float* __restrict__ x) {
    int w = (blockIdx.x * blockDim.x + threadIdx.x) >> 5;
    int lane = threadIdx.x & 31;
    if (w >= NN || lane >= 24) return;
    int start = g_off[w];
    int end = (w + 1 < NN) ? g_off[w + 1] : NE;
    float acc = 0.0f;
    for (int e = start; e < end; e++) {
        int s = g_srcs[e];
        acc = fmaf(g_dinv[s], __ldg(x + (size_t)s * 24 + lane), acc);
    }
    g_agg[(size_t)w * 24 + lane] = acc;
}

// ---------------- fast math (MUFU-based) ----------------
__device__ __forceinline__ float fsigmoid(float x) {
    float e, r;
    asm("ex2.approx.ftz.f32 %0, %1;" : "=f"(e) : "f"(-x * 1.4426950408889634f));
    asm("rcp.approx.ftz.f32 %0, %1;" : "=f"(r) : "f"(1.0f + e));
    return r;
}
__device__ __forceinline__ float ftanh(float x) {
    float r;
    asm("tanh.approx.f32 %0, %1;" : "=f"(r) : "f"(x));
    return r;
}

// ---------------- tf32 helpers ----------------
__device__ __forceinline__ uint32_t tf32c(float x) {
    uint32_t r;
    asm("cvt.rna.tf32.f32 %0, %1;" : "=r"(r) : "f"(x));
    return r;
}

// m16n8k8 row.col tf32 MMA, fp32 accumulate; A fed as raw fp32 (HW truncates)
__device__ __forceinline__ void mma1688f(float* d, const float* a,
                                         uint32_t b0, uint32_t b1) {
    asm volatile(
        "mma.sync.aligned.m16n8k8.row.col.f32.tf32.tf32.f32 "
        "{%0,%1,%2,%3}, {%4,%5,%6,%7}, {%8,%9}, {%0,%1,%2,%3};"
        : "+f"(d[0]), "+f"(d[1]), "+f"(d[2]), "+f"(d[3])
        : "r"(__float_as_uint(a[0])), "r"(__float_as_uint(a[1])),
          "r"(__float_as_uint(a[2])), "r"(__float_as_uint(a[3])),
          "r"(b0), "r"(b1));
}

// column permutation: B fragment n-slot g holds weight row j = 8*nt + perm(g)
// so D slots = tf32 A-fragment column layout (D==A identity, no repack)
__device__ __forceinline__ int permj(int g) { return (g >> 1) + 4 * (g & 1); }

// ---------------- smem layout (bytes) ----------------
#define SM_B1    0          // 128 frags x 32 lanes x 16B = 64KB (rz: K=128,N=128)
#define SM_B2    65536      // 16KB (Wih_n: K=64,N=64)
#define SM_B3    81920      // 16KB (Whh_n)
#define SM_XA    98304      // float2[12][128] = 12KB
#define SM_WG3   110592     // float4[64] : {wg0, wg1, bg, 0}
#define SM_BIAS  111616     // float4[64] : {br, bz, bin, bhn}
#define SM_WFC   112640     // float[64]
#define SM_TOTAL 112896     // 2 CTAs per SM

// 4 warps x 32 nodes; every B LDS.128 feeds 4 MMAs (2 A-sets)
__global__ void __launch_bounds__(THREADS, 2)
k_fused(const float* __restrict__ x,
        const float* __restrict__ W_gcn, const float* __restrict__ b_gcn,
        const float* __restrict__ W_ih,  const float* __restrict__ W_hh,
        const float* __restrict__ b_ih,  const float* __restrict__ b_hh,
        const float* __restrict__ W_fc,  const float* __restrict__ b_fc,
        float* __restrict__ out) {
    extern __shared__ char smem[];
    const int tid  = threadIdx.x;
    const int wid  = tid >> 5;          // 0..3
    const int lane = tid & 31;
    const int gid  = lane >> 2;
    const int tig  = lane & 3;
    const int node0 = blockIdx.x * NPB;
    const int n0 = wid * 32 + gid;      // set0: rows n0, n0+8; set1: n0+16, n0+24

    // ---- build B fragments: ALL tf32 (rounded), column-permuted ----
    for (int i = tid; i < 6144; i += THREADS) {
        uint4 v;
        uint32_t dst;
        if (i < 4096) {                       // B1: rz, 8kt x 16nt
            int f = i >> 5, l = i & 31;
            int kt = f >> 4, nt = f & 15;
            int g = l >> 2, tg = l & 3;
            int j = 8 * nt + permj(g);
            const float* Wr = (kt < 4)
                ? (W_ih + j * 64 + 16 * kt + tg)
                : (W_hh + j * 64 + 16 * (kt - 4) + tg);
            v.x = tf32c(Wr[0]);
            v.y = tf32c(Wr[4]);
            v.z = tf32c(Wr[8]);
            v.w = tf32c(Wr[12]);
            dst = SM_B1 + (uint32_t)(f * 32 + l) * 16;
        } else if (i < 5120) {                // B2: Wih_n
            int ii = i - 4096;
            int f = ii >> 5, l = ii & 31;
            int kt = f >> 3, nt = f & 7;
            int g = l >> 2, tg = l & 3;
            int j = 8 * nt + permj(g);
            const float* Wr = W_ih + (128 + j) * 64 + 16 * kt + tg;
            v.x = tf32c(Wr[0]);
            v.y = tf32c(Wr[4]);
            v.z = tf32c(Wr[8]);
            v.w = tf32c(Wr[12]);
            dst = SM_B2 + (uint32_t)(f * 32 + l) * 16;
        } else {                              // B3: Whh_n
            int ii = i - 5120;
            int f = ii >> 5, l = ii & 31;
            int kt = f >> 3, nt = f & 7;
            int g = l >> 2, tg = l & 3;
            int j = 8 * nt + permj(g);
            const float* Wr = W_hh + (128 + j) * 64 + 16 * kt + tg;
            v.x = tf32c(Wr[0]);
            v.y = tf32c(Wr[4]);
            v.z = tf32c(Wr[8]);
            v.w = tf32c(Wr[12]);
            dst = SM_B3 + (uint32_t)(f * 32 + l) * 16;
        }
        *(uint4*)(smem + dst) = v;
    }

    // ---- XA: dinv*(agg_raw + dinv*x), layout float2[t][n] ----
    float* sXA = (float*)(smem + SM_XA);
    for (int i = tid; i < NPB * 24; i += THREADS) {
        int n = i / 24, cc = i - n * 24;
        int t = cc >> 1, c = cc & 1;
        int node = node0 + n;
        float v = 0.0f;
        if (node < NN) {
            float dv = g_dinv[node];
            v = dv * (g_agg[(size_t)node * 24 + cc] + dv * x[(size_t)node * 24 + cc]);
        }
        sXA[(t * 128 + n) * 2 + c] = v;
    }
    if (tid < 64) {
        float4* wg3 = (float4*)(smem + SM_WG3);
        wg3[tid] = make_float4(W_gcn[tid], W_gcn[64 + tid], b_gcn[tid], 0.0f);
        float4* bia = (float4*)(smem + SM_BIAS);
        bia[tid] = make_float4(b_ih[tid] + b_hh[tid],
                               b_ih[64 + tid] + b_hh[64 + tid],
                               b_ih[128 + tid], b_hh[128 + tid]);
        ((float*)(smem + SM_WFC))[tid] = W_fc[tid];
    }
    __syncthreads();

    const float4* sWG3  = (const float4*)(smem + SM_WG3);
    const float4* sBIAS = (const float4*)(smem + SM_BIAS);
    const float*  sWFC  = (const float*)(smem + SM_WFC);

    // ---- hidden state fp32, tf32 A-fragment layout, 2 sets ----
    float hA[2][8][4];
#pragma unroll
    for (int st = 0; st < 2; st++)
#pragma unroll
        for (int m = 0; m < 8; m++)
#pragma unroll
            for (int q = 0; q < 4; q++) hA[st][m][q] = 0.0f;

#pragma unroll 1
    for (int t = 0; t < TT; t++) {
        float2 xaA = *(const float2*)(sXA + (t * 128 + n0) * 2);
        float2 xaB = *(const float2*)(sXA + (t * 128 + n0 + 8) * 2);
        float2 xaC = *(const float2*)(sXA + (t * 128 + n0 + 16) * 2);
        float2 xaD = *(const float2*)(sXA + (t * 128 + n0 + 24) * 2);

        // ---- S in fp32 A-fragment layout, 2 sets ----
        float sf[2][8][4];
#pragma unroll
        for (int m = 0; m < 8; m++) {
            int kb = 8 * m + tig;
            float4 w0 = sWG3[kb];
            float4 w4 = sWG3[kb + 4];
            sf[0][m][0] = fmaxf(fmaf(xaA.x, w0.x, fmaf(xaA.y, w0.y, w0.z)), 0.0f);
            sf[0][m][1] = fmaxf(fmaf(xaB.x, w0.x, fmaf(xaB.y, w0.y, w0.z)), 0.0f);
            sf[0][m][2] = fmaxf(fmaf(xaA.x, w4.x, fmaf(xaA.y, w4.y, w4.z)), 0.0f);
            sf[0][m][3] = fmaxf(fmaf(xaB.x, w4.x, fmaf(xaB.y, w4.y, w4.z)), 0.0f);
            sf[1][m][0] = fmaxf(fmaf(xaC.x, w0.x, fmaf(xaC.y, w0.y, w0.z)), 0.0f);
            sf[1][m][1] = fmaxf(fmaf(xaD.x, w0.x, fmaf(xaD.y, w0.y, w0.z)), 0.0f);
            sf[1][m][2] = fmaxf(fmaf(xaC.x, w4.x, fmaf(xaC.y, w4.y, w4.z)), 0.0f);
            sf[1][m][3] = fmaxf(fmaf(xaD.x, w4.x, fmaf(xaD.y, w4.y, w4.z)), 0.0f);
        }

        // ---- per-nt: accumulate gates for BOTH sets, nonlinearity, nhA ----
        float nhA[2][8][4];
#pragma unroll
        for (int nt = 0; nt < 8; nt++) {
            float aR[2][4] = {{0,0,0,0},{0,0,0,0}}, aZ[2][4] = {{0,0,0,0},{0,0,0,0}};
            float aI[2][4] = {{0,0,0,0},{0,0,0,0}}, aN[2][4] = {{0,0,0,0},{0,0,0,0}};
#pragma unroll
            for (int kt = 0; kt < 4; kt++) {
                uint4 bR = *(const uint4*)(smem + SM_B1 +
                             (uint32_t)((kt * 16 + nt) * 32 + lane) * 16);
                mma1688f(aR[0], sf[0][2 * kt],     bR.x, bR.y);
                mma1688f(aR[1], sf[1][2 * kt],     bR.x, bR.y);
                mma1688f(aR[0], sf[0][2 * kt + 1], bR.z, bR.w);
                mma1688f(aR[1], sf[1][2 * kt + 1], bR.z, bR.w);
                uint4 bZ = *(const uint4*)(smem + SM_B1 +
                             (uint32_t)((kt * 16 + nt + 8) * 32 + lane) * 16);
                mma1688f(aZ[0], sf[0][2 * kt],     bZ.x, bZ.y);
                mma1688f(aZ[1], sf[1][2 * kt],     bZ.x, bZ.y);
                mma1688f(aZ[0], sf[0][2 * kt + 1], bZ.z, bZ.w);
                mma1688f(aZ[1], sf[1][2 * kt + 1], bZ.z, bZ.w);
                uint4 b2 = *(const uint4*)(smem + SM_B2 +
                             (uint32_t)((kt * 8 + nt) * 32 + lane) * 16);
                mma1688f(aI[0], sf[0][2 * kt],     b2.x, b2.y);
                mma1688f(aI[1], sf[1][2 * kt],     b2.x, b2.y);
                mma1688f(aI[0], sf[0][2 * kt + 1], b2.z, b2.w);
                mma1688f(aI[1], sf[1][2 * kt + 1], b2.z, b2.w);
                uint4 b3 = *(const uint4*)(smem + SM_B3 +
                             (uint32_t)((kt * 8 + nt) * 32 + lane) * 16);
                mma1688f(aN[0], hA[0][2 * kt],     b3.x, b3.y);
                mma1688f(aN[1], hA[1][2 * kt],     b3.x, b3.y);
                mma1688f(aN[0], hA[0][2 * kt + 1], b3.z, b3.w);
                mma1688f(aN[1], hA[1][2 * kt + 1], b3.z, b3.w);
            }
#pragma unroll
            for (int kt = 0; kt < 4; kt++) {
                uint4 cR = *(const uint4*)(smem + SM_B1 +
                             (uint32_t)(((kt + 4) * 16 + nt) * 32 + lane) * 16);
                mma1688f(aR[0], hA[0][2 * kt],     cR.x, cR.y);
                mma1688f(aR[1], hA[1][2 * kt],     cR.x, cR.y);
                mma1688f(aR[0], hA[0][2 * kt + 1], cR.z, cR.w);
                mma1688f(aR[1], hA[1][2 * kt + 1], cR.z, cR.w);
                uint4 cZ = *(const uint4*)(smem + SM_B1 +
                             (uint32_t)(((kt + 4) * 16 + nt + 8) * 32 + lane) * 16);
                mma1688f(aZ[0], hA[0][2 * kt],     cZ.x, cZ.y);
                mma1688f(aZ[1], hA[1][2 * kt],     cZ.x, cZ.y);
                mma1688f(aZ[0], hA[0][2 * kt + 1], cZ.z, cZ.w);
                mma1688f(aZ[1], hA[1][2 * kt + 1], cZ.z, cZ.w);
            }
            int jb = 8 * nt + tig;
            float4 bj0 = sBIAS[jb];        // j = tig
            float4 bj1 = sBIAS[jb + 4];    // j = tig+4
#pragma unroll
            for (int st = 0; st < 2; st++) {
                // q0: rowA,jt -> nhA[nt][0]; q1: rowA,jt+4 -> [2];
                // q2: rowB,jt -> [1]; q3: rowB,jt+4 -> [3]
                {
                    float r = fsigmoid(aR[st][0] + bj0.x);
                    float z = fsigmoid(aZ[st][0] + bj0.y);
                    float nn = ftanh(fmaf(r, aN[st][0] + bj0.w, aI[st][0] + bj0.z));
                    nhA[st][nt][0] = fmaf(z, hA[st][nt][0] - nn, nn);
                }
                {
                    float r = fsigmoid(aR[st][1] + bj1.x);
                    float z = fsigmoid(aZ[st][1] + bj1.y);
                    float nn = ftanh(fmaf(r, aN[st][1] + bj1.w, aI[st][1] + bj1.z));
                    nhA[st][nt][2] = fmaf(z, hA[st][nt][2] - nn, nn);
                }
                {
                    float r = fsigmoid(aR[st][2] + bj0.x);
                    float z = fsigmoid(aZ[st][2] + bj0.y);
                    float nn = ftanh(fmaf(r, aN[st][2] + bj0.w, aI[st][2] + bj0.z));
                    nhA[st][nt][1] = fmaf(z, hA[st][nt][1] - nn, nn);
                }
                {
                    float r = fsigmoid(aR[st][3] + bj1.x);
                    float z = fsigmoid(aZ[st][3] + bj1.y);
                    float nn = ftanh(fmaf(r, aN[st][3] + bj1.w, aI[st][3] + bj1.z));
                    nhA[st][nt][3] = fmaf(z, hA[st][nt][3] - nn, nn);
                }
            }
        }
#pragma unroll
        for (int st = 0; st < 2; st++)
#pragma unroll
            for (int m = 0; m < 8; m++)
#pragma unroll
                for (int q = 0; q < 4; q++) hA[st][m][q] = nhA[st][m][q];
    }

    // ---- FC readout: 4 node rows per thread ----
    float pA = 0.0f, pB = 0.0f, pC = 0.0f, pD = 0.0f;
#pragma unroll
    for (int nt = 0; nt < 8; nt++) {
        int jb = 8 * nt + tig;
        float w0 = sWFC[jb], w1 = sWFC[jb + 4];
        pA = fmaf(hA[0][nt][0], w0, fmaf(hA[0][nt][2], w1, pA));
        pB = fmaf(hA[0][nt][1], w0, fmaf(hA[0][nt][3], w1, pB));
        pC = fmaf(hA[1][nt][0], w0, fmaf(hA[1][nt][2], w1, pC));
        pD = fmaf(hA[1][nt][1], w0, fmaf(hA[1][nt][3], w1, pD));
    }
    pA += __shfl_xor_sync(0xFFFFFFFF, pA, 1);
    pA += __shfl_xor_sync(0xFFFFFFFF, pA, 2);
    pB += __shfl_xor_sync(0xFFFFFFFF, pB, 1);
    pB += __shfl_xor_sync(0xFFFFFFFF, pB, 2);
    pC += __shfl_xor_sync(0xFFFFFFFF, pC, 1);
    pC += __shfl_xor_sync(0xFFFFFFFF, pC, 2);
    pD += __shfl_xor_sync(0xFFFFFFFF, pD, 1);
    pD += __shfl_xor_sync(0xFFFFFFFF, pD, 2);
    if (tig == 0) {
        float bfc = b_fc[0];
        int nA = node0 + n0, nB = nA + 8, nC = nA + 16, nD = nA + 24;
        if (nA < NN) out[nA] = pA + bfc;
        if (nB < NN) out[nB] = pB + bfc;
        if (nC < NN) out[nC] = pC + bfc;
        if (nD < NN) out[nD] = pD + bfc;
    }
}

// ---------------- launch ----------------
extern "C" void kernel_launch(void* const* d_in, const int* in_sizes, int n_in,
                              void* d_out, int out_size) {
    const float* x     = (const float*)d_in[0];
    const int*   ei32  = (const int*)d_in[1];
    const float* W_gcn = (const float*)d_in[2];
    const float* b_gcn = (const float*)d_in[3];
    const float* W_ih  = (const float*)d_in[4];
    const float* W_hh  = (const float*)d_in[5];
    const float* b_ih  = (const float*)d_in[6];
    const float* b_hh  = (const float*)d_in[7];
    const float* W_fc  = (const float*)d_in[8];
    const float* b_fc  = (const float*)d_in[9];
    float* out = (float*)d_out;

    static bool attr_set = false;
    if (!attr_set) {
        cudaFuncSetAttribute(k_fused, cudaFuncAttributeMaxDynamicSharedMemorySize,
                             SM_TOTAL);
        attr_set = true;
    }

    k_initprobe<<<SCAN_BLOCKS, 256>>>(ei32);
    k_count<<<(NE + 255) / 256, 256>>>(ei32);
    k_scan1<<<SCAN_BLOCKS, 256>>>();
    k_scan2<<<1, 256>>>();
    k_scan3<<<SCAN_BLOCKS, 256>>>();
    k_fill<<<(NE + 255) / 256, 256>>>(ei32);
    k_gather<<<(NN * 32 + 255) / 256, 256>>>(x);
    k_fused<<<(NN + NPB - 1) / NPB, THREADS, SM_TOTAL>>>(
        x, W_gcn, b_gcn, W_ih, W_hh, b_ih, b_hh, W_fc, b_fc, out);
}